// round 2
// baseline (speedup 1.0000x reference)
#include <cuda_runtime.h>
#include <cstddef>

#define D 128
#define EPS_BN 1e-5f
#define MAX_NODES 100000
#define CAP 96          // bucket capacity per row (Poisson(16) degrees; P(>=96) ~ 1e-43)

// ---------------- scratch (__device__ globals; allocation-free rule) --------
__device__ float  g_hA[(size_t)MAX_NODES * D];           // 51.2 MB
__device__ float  g_hB[(size_t)MAX_NODES * D];           // 51.2 MB
__device__ float2 g_edges[(size_t)MAX_NODES * CAP];      // 76.8 MB (colbits, weight)
__device__ int    g_cnt[MAX_NODES];                      // per-row degree cursor
__device__ float  g_stats[4 * D];                        // layer1: [0..2D), layer2: [2D..4D)
__device__ float  g_scale[D];
__device__ float  g_shift[D];

// ---------------- f32x2 helpers ---------------------------------------------
__device__ __forceinline__ unsigned long long pack2(float lo, float hi) {
    unsigned long long r;
    asm("mov.b64 %0, {%1, %2};" : "=l"(r) : "f"(lo), "f"(hi));
    return r;
}
__device__ __forceinline__ void unpack2(unsigned long long v, float& lo, float& hi) {
    asm("mov.b64 {%0, %1}, %2;" : "=f"(lo), "=f"(hi) : "l"(v));
}
__device__ __forceinline__ unsigned long long ffma2(
    unsigned long long a, unsigned long long b, unsigned long long c) {
    unsigned long long d;
    asm("fma.rn.f32x2 %0, %1, %2, %3;" : "=l"(d) : "l"(a), "l"(b), "l"(c));
    return d;
}

// ---------------- init: zero cursors + stats --------------------------------
__global__ void init_kernel(int* __restrict__ cnt, float* __restrict__ stats, int n) {
    int i = blockIdx.x * blockDim.x + threadIdx.x;
    int stride = gridDim.x * blockDim.x;
    for (int j = i; j < n; j += stride) cnt[j] = 0;
    if (i < 4 * D) stats[i] = 0.0f;
}

// ---------------- scatter edges into per-row buckets ------------------------
__global__ void scatter_kernel(const int* __restrict__ row, const int* __restrict__ col,
                               const float* __restrict__ w, float2* __restrict__ edges,
                               int* __restrict__ cnt, int nedges) {
    int e = blockIdx.x * blockDim.x + threadIdx.x;
    if (e >= nedges) return;
    int r = row[e];
    int slot = atomicAdd(&cnt[r], 1);
    if (slot < CAP)
        edges[(size_t)r * CAP + slot] = make_float2(__int_as_float(col[e]), w[e]);
}

// ---------------- GEMM: Y = act(X) @ W + b  (f32x2 packed FMA) --------------
// act(v) = relu(v*scale[c] + shift[c]) when use_bn, else identity.
// Block 256 threads, 64x128 tile. Each thread: 8 rows (4 packed pairs) x 4 cols.
__global__ __launch_bounds__(256) void gemm_kernel(
    const float* __restrict__ X, const float* __restrict__ W,
    const float* __restrict__ bias,
    const float* __restrict__ bn_scale, const float* __restrict__ bn_shift,
    float* __restrict__ Y, int nrows, int use_bn)
{
    __shared__ __align__(16) float xs[32][66];    // [k][row], stride 66 keeps 8B align
    __shared__ __align__(16) float ws[32][128];   // [k][col]

    int t  = threadIdx.x;
    int tx = t & 31;        // cols tx*4 .. tx*4+3
    int ty = t >> 5;        // rows ty*8 .. ty*8+7 (4 packed pairs)
    int row0 = blockIdx.x * 64;

    unsigned long long acc[4][4];
#pragma unroll
    for (int i = 0; i < 4; i++)
#pragma unroll
        for (int j = 0; j < 4; j++) acc[i][j] = 0ULL;

    for (int k0 = 0; k0 < D; k0 += 32) {
        // W tile (32 x 128) via float4
#pragma unroll
        for (int i = 0; i < 4; i++) {
            int fi = t + i * 256;
            int k  = fi >> 5;
            int c4 = fi & 31;
            *(float4*)&ws[k][c4 * 4] =
                *(const float4*)&W[(size_t)(k0 + k) * D + c4 * 4];
        }
        // X tile (64 rows x 32 k), transposed into xs[k][r], BN+ReLU fused
#pragma unroll
        for (int i = 0; i < 8; i++) {
            int fi = t + i * 256;
            int r  = fi >> 5;     // 0..63
            int k  = fi & 31;     // 0..31
            int row = row0 + r;
            float v = 0.0f;
            if (row < nrows) {
                v = X[(size_t)row * D + k0 + k];
                if (use_bn)
                    v = fmaxf(v * bn_scale[k0 + k] + bn_shift[k0 + k], 0.0f);
            }
            xs[k][r] = v;
        }
        __syncthreads();

#pragma unroll
        for (int k = 0; k < 32; k++) {
            float4 wv = *(const float4*)&ws[k][tx * 4];
            unsigned long long w2[4];
            w2[0] = pack2(wv.x, wv.x);
            w2[1] = pack2(wv.y, wv.y);
            w2[2] = pack2(wv.z, wv.z);
            w2[3] = pack2(wv.w, wv.w);
#pragma unroll
            for (int rp = 0; rp < 4; rp++) {
                unsigned long long xv =
                    *(const unsigned long long*)&xs[k][ty * 8 + rp * 2];
#pragma unroll
                for (int c = 0; c < 4; c++)
                    acc[rp][c] = ffma2(xv, w2[c], acc[rp][c]);
            }
        }
        __syncthreads();
    }

    float4 bv = *(const float4*)&bias[tx * 4];
#pragma unroll
    for (int rp = 0; rp < 4; rp++) {
        int re = row0 + ty * 8 + rp * 2;
        float4 oe, oo;
        unpack2(acc[rp][0], oe.x, oo.x);
        unpack2(acc[rp][1], oe.y, oo.y);
        unpack2(acc[rp][2], oe.z, oo.z);
        unpack2(acc[rp][3], oe.w, oo.w);
        oe.x += bv.x; oe.y += bv.y; oe.z += bv.z; oe.w += bv.w;
        oo.x += bv.x; oo.y += bv.y; oo.z += bv.z; oo.w += bv.w;
        if (re < nrows)     *(float4*)&Y[(size_t)re * D + tx * 4] = oe;
        if (re + 1 < nrows) *(float4*)&Y[(size_t)(re + 1) * D + tx * 4] = oo;
    }
}

// ---------------- SpMM (bucketed CSR): warp per row, register accumulate ----
// Also accumulates BN column stats (sum, sumsq) when with_stats != 0.
__global__ __launch_bounds__(256) void spmm_kernel(
    const int* __restrict__ cnt, const float2* __restrict__ edges,
    const float* __restrict__ H, float* __restrict__ out,
    float* __restrict__ stats, int nrows, int with_stats)
{
    int lane  = threadIdx.x & 31;
    int warp  = blockIdx.x * 8 + (threadIdx.x >> 5);
    int nwarp = gridDim.x * 8;

    float4 ssum = make_float4(0.f, 0.f, 0.f, 0.f);
    float4 ssq  = make_float4(0.f, 0.f, 0.f, 0.f);

    for (int r = warp; r < nrows; r += nwarp) {
        int deg = __ldg(&cnt[r]);
        float4 acc = make_float4(0.f, 0.f, 0.f, 0.f);
        const float2* bucket = &edges[(size_t)r * CAP];

        for (int base = 0; base < deg; base += 32) {
            int m = min(32, deg - base);
            float2 e = make_float2(0.f, 0.f);
            if (base + lane < deg) e = bucket[base + lane];
            int   ci = __float_as_int(e.x);
            float wi = e.y;
            for (int j = 0; j < m; j++) {
                int   c = __shfl_sync(0xffffffffu, ci, j);
                float w = __shfl_sync(0xffffffffu, wi, j);
                float4 v = *(const float4*)&H[(size_t)c * D + lane * 4];
                acc.x += w * v.x;
                acc.y += w * v.y;
                acc.z += w * v.z;
                acc.w += w * v.w;
            }
        }

        *(float4*)&out[(size_t)r * D + lane * 4] = acc;
        if (with_stats) {
            ssum.x += acc.x; ssum.y += acc.y; ssum.z += acc.z; ssum.w += acc.w;
            ssq.x += acc.x * acc.x; ssq.y += acc.y * acc.y;
            ssq.z += acc.z * acc.z; ssq.w += acc.w * acc.w;
        }
    }

    if (with_stats) {
        atomicAdd(&stats[lane * 4 + 0], ssum.x);
        atomicAdd(&stats[lane * 4 + 1], ssum.y);
        atomicAdd(&stats[lane * 4 + 2], ssum.z);
        atomicAdd(&stats[lane * 4 + 3], ssum.w);
        atomicAdd(&stats[D + lane * 4 + 0], ssq.x);
        atomicAdd(&stats[D + lane * 4 + 1], ssq.y);
        atomicAdd(&stats[D + lane * 4 + 2], ssq.z);
        atomicAdd(&stats[D + lane * 4 + 3], ssq.w);
    }
}

// ---------------- BN finalize ------------------------------------------------
__global__ void bnfinal_kernel(const float* __restrict__ stats,
                               const float* __restrict__ g,
                               const float* __restrict__ be,
                               float* __restrict__ scale, float* __restrict__ shift,
                               float inv_n) {
    int c = threadIdx.x;
    float m   = stats[c] * inv_n;
    float var = stats[D + c] * inv_n - m * m;
    float rs  = rsqrtf(var + EPS_BN);
    float sc  = g[c] * rs;
    scale[c] = sc;
    shift[c] = be[c] - m * sc;
}

// ---------------- launch -----------------------------------------------------
extern "C" void kernel_launch(void* const* d_in, const int* in_sizes, int n_in,
                              void* d_out, int out_size)
{
    const float* x   = (const float*)d_in[0];
    const float* ew  = (const float*)d_in[1];
    const float* W0  = (const float*)d_in[2];
    const float* b0  = (const float*)d_in[3];
    const float* g0  = (const float*)d_in[4];
    const float* be0 = (const float*)d_in[5];
    const float* W1  = (const float*)d_in[6];
    const float* b1  = (const float*)d_in[7];
    const float* g1  = (const float*)d_in[8];
    const float* be1 = (const float*)d_in[9];
    const float* W2  = (const float*)d_in[10];
    const float* b2  = (const float*)d_in[11];
    const int*   row = (const int*)d_in[12];
    const int*   col = (const int*)d_in[13];
    float* out = (float*)d_out;

    int nrows  = in_sizes[0] / D;
    int nedges = in_sizes[1];
    float inv_n = 1.0f / (float)nrows;

    float  *hA, *hB, *stats, *scale, *shift;
    float2 *edges;
    int    *cnt;
    cudaGetSymbolAddress((void**)&hA, g_hA);
    cudaGetSymbolAddress((void**)&hB, g_hB);
    cudaGetSymbolAddress((void**)&edges, g_edges);
    cudaGetSymbolAddress((void**)&cnt, g_cnt);
    cudaGetSymbolAddress((void**)&stats, g_stats);
    cudaGetSymbolAddress((void**)&scale, g_scale);
    cudaGetSymbolAddress((void**)&shift, g_shift);

    dim3 gemm_grid((nrows + 63) / 64);
    int  spmm_grid = 2048;                 // 8 warps/block, grid-stride over rows

    // build per-row edge buckets (inside the capture; deterministic sums)
    init_kernel<<<512, 256>>>(cnt, stats, nrows);
    scatter_kernel<<<(nedges + 255) / 256, 256>>>(row, col, ew, edges, cnt, nedges);

    // ---- layer 1 ----
    gemm_kernel<<<gemm_grid, 256>>>(x, W0, b0, nullptr, nullptr, hA, nrows, 0);
    spmm_kernel<<<spmm_grid, 256>>>(cnt, edges, hA, hB, stats, nrows, 1);
    bnfinal_kernel<<<1, D>>>(stats, g0, be0, scale, shift, inv_n);

    // ---- layer 2 (BN+ReLU fused into GEMM x-load) ----
    gemm_kernel<<<gemm_grid, 256>>>(hB, W1, b1, scale, shift, hA, nrows, 1);
    spmm_kernel<<<spmm_grid, 256>>>(cnt, edges, hA, hB, stats + 2 * D, nrows, 1);
    bnfinal_kernel<<<1, D>>>(stats + 2 * D, g1, be1, scale, shift, inv_n);

    // ---- layer 3 (no BN/act after; writes d_out directly, all rows) ----
    gemm_kernel<<<gemm_grid, 256>>>(hB, W2, b2, scale, shift, hA, nrows, 1);
    spmm_kernel<<<spmm_grid, 256>>>(cnt, edges, hA, out, nullptr, nrows, 0);
}

// round 3
// speedup vs baseline: 3.4282x; 3.4282x over previous
#include <cuda_runtime.h>
#include <cstddef>

#define D 128
#define EPS_BN 1e-5f
#define MAX_NODES 100000
#define CAP 96          // bucket capacity per row (Poisson(16) degrees; P(>=96) ~ 1e-43)

// ---------------- scratch (__device__ globals; allocation-free rule) --------
__device__ float  g_hA[(size_t)MAX_NODES * D];           // 51.2 MB
__device__ float  g_hB[(size_t)MAX_NODES * D];           // 51.2 MB
__device__ float2 g_edges[(size_t)MAX_NODES * CAP];      // 76.8 MB (colbits, weight)
__device__ int    g_cnt[MAX_NODES];                      // per-row degree cursor
__device__ float  g_stats[4 * D];                        // layer1: [0..2D), layer2: [2D..4D)
__device__ float  g_scale[D];
__device__ float  g_shift[D];

// ---------------- f32x2 helpers ---------------------------------------------
__device__ __forceinline__ unsigned long long pack2(float lo, float hi) {
    unsigned long long r;
    asm("mov.b64 %0, {%1, %2};" : "=l"(r) : "f"(lo), "f"(hi));
    return r;
}
__device__ __forceinline__ void unpack2(unsigned long long v, float& lo, float& hi) {
    asm("mov.b64 {%0, %1}, %2;" : "=f"(lo), "=f"(hi) : "l"(v));
}
__device__ __forceinline__ unsigned long long ffma2(
    unsigned long long a, unsigned long long b, unsigned long long c) {
    unsigned long long d;
    asm("fma.rn.f32x2 %0, %1, %2, %3;" : "=l"(d) : "l"(a), "l"(b), "l"(c));
    return d;
}

// ---------------- init: zero cursors + stats --------------------------------
__global__ void init_kernel(int* __restrict__ cnt, float* __restrict__ stats, int n) {
    int i = blockIdx.x * blockDim.x + threadIdx.x;
    int stride = gridDim.x * blockDim.x;
    for (int j = i; j < n; j += stride) cnt[j] = 0;
    if (i < 4 * D) stats[i] = 0.0f;
}

// ---------------- scatter edges into per-row buckets ------------------------
__global__ void scatter_kernel(const int* __restrict__ row, const int* __restrict__ col,
                               const float* __restrict__ w, float2* __restrict__ edges,
                               int* __restrict__ cnt, int nedges) {
    int e = blockIdx.x * blockDim.x + threadIdx.x;
    if (e >= nedges) return;
    int r = row[e];
    int slot = atomicAdd(&cnt[r], 1);
    if (slot < CAP)
        edges[(size_t)r * CAP + slot] = make_float2(__int_as_float(col[e]), w[e]);
}

// ---------------- GEMM: Y = act(X) @ W + b  (f32x2 packed FMA) --------------
__global__ __launch_bounds__(256) void gemm_kernel(
    const float* __restrict__ X, const float* __restrict__ W,
    const float* __restrict__ bias,
    const float* __restrict__ bn_scale, const float* __restrict__ bn_shift,
    float* __restrict__ Y, int nrows, int use_bn)
{
    __shared__ __align__(16) float xs[32][66];    // [k][row], stride 66 keeps 8B align
    __shared__ __align__(16) float ws[32][128];   // [k][col]

    int t  = threadIdx.x;
    int tx = t & 31;        // cols tx*4 .. tx*4+3
    int ty = t >> 5;        // rows ty*8 .. ty*8+7 (4 packed pairs)
    int row0 = blockIdx.x * 64;

    unsigned long long acc[4][4];
#pragma unroll
    for (int i = 0; i < 4; i++)
#pragma unroll
        for (int j = 0; j < 4; j++) acc[i][j] = 0ULL;

    for (int k0 = 0; k0 < D; k0 += 32) {
#pragma unroll
        for (int i = 0; i < 4; i++) {
            int fi = t + i * 256;
            int k  = fi >> 5;
            int c4 = fi & 31;
            *(float4*)&ws[k][c4 * 4] =
                *(const float4*)&W[(size_t)(k0 + k) * D + c4 * 4];
        }
#pragma unroll
        for (int i = 0; i < 8; i++) {
            int fi = t + i * 256;
            int r  = fi >> 5;     // 0..63
            int k  = fi & 31;     // 0..31
            int row = row0 + r;
            float v = 0.0f;
            if (row < nrows) {
                v = X[(size_t)row * D + k0 + k];
                if (use_bn)
                    v = fmaxf(v * bn_scale[k0 + k] + bn_shift[k0 + k], 0.0f);
            }
            xs[k][r] = v;
        }
        __syncthreads();

#pragma unroll
        for (int k = 0; k < 32; k++) {
            float4 wv = *(const float4*)&ws[k][tx * 4];
            unsigned long long w2[4];
            w2[0] = pack2(wv.x, wv.x);
            w2[1] = pack2(wv.y, wv.y);
            w2[2] = pack2(wv.z, wv.z);
            w2[3] = pack2(wv.w, wv.w);
#pragma unroll
            for (int rp = 0; rp < 4; rp++) {
                unsigned long long xv =
                    *(const unsigned long long*)&xs[k][ty * 8 + rp * 2];
#pragma unroll
                for (int c = 0; c < 4; c++)
                    acc[rp][c] = ffma2(xv, w2[c], acc[rp][c]);
            }
        }
        __syncthreads();
    }

    float4 bv = *(const float4*)&bias[tx * 4];
#pragma unroll
    for (int rp = 0; rp < 4; rp++) {
        int re = row0 + ty * 8 + rp * 2;
        float4 oe, oo;
        unpack2(acc[rp][0], oe.x, oo.x);
        unpack2(acc[rp][1], oe.y, oo.y);
        unpack2(acc[rp][2], oe.z, oo.z);
        unpack2(acc[rp][3], oe.w, oo.w);
        oe.x += bv.x; oe.y += bv.y; oe.z += bv.z; oe.w += bv.w;
        oo.x += bv.x; oo.y += bv.y; oo.z += bv.z; oo.w += bv.w;
        if (re < nrows)     *(float4*)&Y[(size_t)re * D + tx * 4] = oe;
        if (re + 1 < nrows) *(float4*)&Y[(size_t)(re + 1) * D + tx * 4] = oo;
    }
}

// ---------------- SpMM (bucketed CSR): warp per row, 8-deep load batching ---
// MLP restored: per batch, 8 shfl-broadcasts then 8 INDEPENDENT LDG.128s,
// then 8 FMAs. Zero-padded tail lanes carry (col=0, w=0) so padded loads are
// valid-but-ignored. BN column stats pre-reduced in shared memory.
__global__ __launch_bounds__(256) void spmm_kernel(
    const int* __restrict__ cnt, const float2* __restrict__ edges,
    const float* __restrict__ H, float* __restrict__ out,
    float* __restrict__ stats, int nrows, int with_stats)
{
    __shared__ float s_st[2 * D];

    int lane  = threadIdx.x & 31;
    int warp  = blockIdx.x * 8 + (threadIdx.x >> 5);
    int nwarp = gridDim.x * 8;

    if (with_stats) {
        for (int i = threadIdx.x; i < 2 * D; i += 256) s_st[i] = 0.0f;
        __syncthreads();
    }

    float4 ssum = make_float4(0.f, 0.f, 0.f, 0.f);
    float4 ssq  = make_float4(0.f, 0.f, 0.f, 0.f);

    for (int r = warp; r < nrows; r += nwarp) {
        int deg = __ldg(&cnt[r]);
        float4 acc = make_float4(0.f, 0.f, 0.f, 0.f);
        const float2* bucket = &edges[(size_t)r * CAP];

        for (int base = 0; base < deg; base += 32) {
            float2 e = make_float2(0.0f, 0.0f);   // pad: col 0 (valid), weight 0
            if (base + lane < deg) e = bucket[base + lane];
            int   ci = __float_as_int(e.x);
            float wi = e.y;
            int   m  = min(32, deg - base);

            for (int b2 = 0; b2 < m; b2 += 8) {
                int   cc[8];
                float ww[8];
#pragma unroll
                for (int jj = 0; jj < 8; jj++) {
                    cc[jj] = __shfl_sync(0xffffffffu, ci, b2 + jj);
                    ww[jj] = __shfl_sync(0xffffffffu, wi, b2 + jj);
                }
                float4 v[8];
#pragma unroll
                for (int jj = 0; jj < 8; jj++)
                    v[jj] = *(const float4*)&H[(size_t)cc[jj] * D + lane * 4];
#pragma unroll
                for (int jj = 0; jj < 8; jj++) {
                    acc.x += ww[jj] * v[jj].x;
                    acc.y += ww[jj] * v[jj].y;
                    acc.z += ww[jj] * v[jj].z;
                    acc.w += ww[jj] * v[jj].w;
                }
            }
        }

        *(float4*)&out[(size_t)r * D + lane * 4] = acc;
        if (with_stats) {
            ssum.x += acc.x; ssum.y += acc.y; ssum.z += acc.z; ssum.w += acc.w;
            ssq.x += acc.x * acc.x; ssq.y += acc.y * acc.y;
            ssq.z += acc.z * acc.z; ssq.w += acc.w * acc.w;
        }
    }

    if (with_stats) {
        atomicAdd(&s_st[lane * 4 + 0], ssum.x);
        atomicAdd(&s_st[lane * 4 + 1], ssum.y);
        atomicAdd(&s_st[lane * 4 + 2], ssum.z);
        atomicAdd(&s_st[lane * 4 + 3], ssum.w);
        atomicAdd(&s_st[D + lane * 4 + 0], ssq.x);
        atomicAdd(&s_st[D + lane * 4 + 1], ssq.y);
        atomicAdd(&s_st[D + lane * 4 + 2], ssq.z);
        atomicAdd(&s_st[D + lane * 4 + 3], ssq.w);
        __syncthreads();
        for (int i = threadIdx.x; i < 2 * D; i += 256)
            atomicAdd(&stats[i], s_st[i]);
    }
}

// ---------------- BN finalize ------------------------------------------------
__global__ void bnfinal_kernel(const float* __restrict__ stats,
                               const float* __restrict__ g,
                               const float* __restrict__ be,
                               float* __restrict__ scale, float* __restrict__ shift,
                               float inv_n) {
    int c = threadIdx.x;
    float m   = stats[c] * inv_n;
    float var = stats[D + c] * inv_n - m * m;
    float rs  = rsqrtf(var + EPS_BN);
    float sc  = g[c] * rs;
    scale[c] = sc;
    shift[c] = be[c] - m * sc;
}

// ---------------- launch -----------------------------------------------------
extern "C" void kernel_launch(void* const* d_in, const int* in_sizes, int n_in,
                              void* d_out, int out_size)
{
    const float* x   = (const float*)d_in[0];
    const float* ew  = (const float*)d_in[1];
    const float* W0  = (const float*)d_in[2];
    const float* b0  = (const float*)d_in[3];
    const float* g0  = (const float*)d_in[4];
    const float* be0 = (const float*)d_in[5];
    const float* W1  = (const float*)d_in[6];
    const float* b1  = (const float*)d_in[7];
    const float* g1  = (const float*)d_in[8];
    const float* be1 = (const float*)d_in[9];
    const float* W2  = (const float*)d_in[10];
    const float* b2  = (const float*)d_in[11];
    const int*   row = (const int*)d_in[12];
    const int*   col = (const int*)d_in[13];
    float* out = (float*)d_out;

    int nrows  = in_sizes[0] / D;
    int nedges = in_sizes[1];
    float inv_n = 1.0f / (float)nrows;

    float  *hA, *hB, *stats, *scale, *shift;
    float2 *edges;
    int    *cnt;
    cudaGetSymbolAddress((void**)&hA, g_hA);
    cudaGetSymbolAddress((void**)&hB, g_hB);
    cudaGetSymbolAddress((void**)&edges, g_edges);
    cudaGetSymbolAddress((void**)&cnt, g_cnt);
    cudaGetSymbolAddress((void**)&stats, g_stats);
    cudaGetSymbolAddress((void**)&scale, g_scale);
    cudaGetSymbolAddress((void**)&shift, g_shift);

    dim3 gemm_grid((nrows + 63) / 64);
    int  spmm_grid = 2048;                 // 8 warps/block, grid-stride over rows

    // build per-row edge buckets (inside the capture; deterministic per replay)
    init_kernel<<<512, 256>>>(cnt, stats, nrows);
    scatter_kernel<<<(nedges + 255) / 256, 256>>>(row, col, ew, edges, cnt, nedges);

    // ---- layer 1 ----
    gemm_kernel<<<gemm_grid, 256>>>(x, W0, b0, nullptr, nullptr, hA, nrows, 0);
    spmm_kernel<<<spmm_grid, 256>>>(cnt, edges, hA, hB, stats, nrows, 1);
    bnfinal_kernel<<<1, D>>>(stats, g0, be0, scale, shift, inv_n);

    // ---- layer 2 (BN+ReLU fused into GEMM x-load) ----
    gemm_kernel<<<gemm_grid, 256>>>(hB, W1, b1, scale, shift, hA, nrows, 1);
    spmm_kernel<<<spmm_grid, 256>>>(cnt, edges, hA, hB, stats + 2 * D, nrows, 1);
    bnfinal_kernel<<<1, D>>>(stats + 2 * D, g1, be1, scale, shift, inv_n);

    // ---- layer 3 (no BN/act after; writes d_out directly) ----
    gemm_kernel<<<gemm_grid, 256>>>(hB, W2, b2, scale, shift, hA, nrows, 1);
    spmm_kernel<<<spmm_grid, 256>>>(cnt, edges, hA, out, nullptr, nrows, 0);
}